// round 13
// baseline (speedup 1.0000x reference)
#include <cuda_runtime.h>
#include <cuda_bf16.h>
#include <math.h>

// Problem constants
#define BATCH   2
#define SEQ     2048
#define DMODEL  1024
#define NHEAD   16
#define DH      64
#define HALF    32
#define MROWS   (BATCH * SEQ)     // 4096 tokens
#define BH      (BATCH * NHEAD)   // 32

// Scratch (device globals; no allocation allowed)
__device__ float g_q[(size_t)BH * SEQ * DH];        // 16 MB
__device__ float g_k[(size_t)BH * SEQ * DH];        // 16 MB
__device__ float g_v[(size_t)BH * SEQ * DH];        // 16 MB
__device__ float g_attn[(size_t)MROWS * DMODEL];    // 16 MB
__device__ float g_cos[SEQ * HALF];
__device__ float g_sin[SEQ * HALF];

// ---------------------------------------------------------------------------
// RoPE cos/sin table. Matches reference: inv_freq = theta^(-2j/64) (fp32),
// ang = fp32(pos * inv_freq), then accurate cos/sin of that fp32 angle.
// ---------------------------------------------------------------------------
__global__ void rope_table_kernel(const int* __restrict__ pos) {
    int i = blockIdx.x * blockDim.x + threadIdx.x;
    if (i >= SEQ * HALF) return;
    int s = i >> 5;
    int j = i & 31;
    double invd = pow(10000.0, -(double)(2 * j) / (double)DH);
    float invf = (float)invd;
    float ang = (float)pos[s] * invf;     // exact fp32 product, like reference
    double a = (double)ang;
    g_cos[i] = (float)cos(a);
    g_sin[i] = (float)sin(a);
}

// ---------------------------------------------------------------------------
// Apply RoPE in place to g_q and g_k. Pairing is adjacent elements (2j, 2j+1).
// ---------------------------------------------------------------------------
__global__ void rope_apply_kernel() {
    int i = blockIdx.x * blockDim.x + threadIdx.x;
    const int total = BH * SEQ * HALF;   // 2,097,152
    if (i >= total) return;
    int j  = i & 31;
    int s  = (i >> 5) & (SEQ - 1);
    int bh = i >> 16;                    // / (SEQ*HALF)
    float c  = g_cos[(s << 5) + j];
    float sn = g_sin[(s << 5) + j];
    size_t base = (((size_t)bh * SEQ) + s) * DH + 2 * j;
    float2 q = *(float2*)(g_q + base);
    float2 k = *(float2*)(g_k + base);
    float2 qo, ko;
    qo.x = q.x * c - q.y * sn;  qo.y = q.x * sn + q.y * c;
    ko.x = k.x * c - k.y * sn;  ko.y = k.x * sn + k.y * c;
    *(float2*)(g_q + base) = qo;
    *(float2*)(g_k + base) = ko;
}

// ---------------------------------------------------------------------------
// SGEMM: C[m,n] = sum_k A[m,k] * Bw[n,k]   (both operands K-major row-major)
// 128x128 tile, BK=8, 256 threads, 8x8 microtile in 4 quadrants (float4 LDS,
// conflict-free), double-buffered smem with register prefetch.
// EPI=0: scatter into g_q/g_k/g_v ([B,H,S,dh] layout). EPI=1: plain row-major C.
// ---------------------------------------------------------------------------
#define BM 128
#define BN 128
#define BK 8

template <int EPI>
__global__ __launch_bounds__(256) void sgemm_kernel(
    const float* __restrict__ A, const float* __restrict__ Bw,
    float* __restrict__ C, int M, int N, int K)
{
    __shared__ float As[2][BK][BM];
    __shared__ float Bs[2][BK][BN];

    const float* Abase = (EPI == 1) ? (const float*)g_attn : A;

    int tid = threadIdx.x;
    int m0 = blockIdx.y * BM;
    int n0 = blockIdx.x * BN;

    int lrow = tid >> 1;              // 0..127
    int lk4  = (tid & 1) * 4;         // 0 or 4
    const float* Ap = Abase + (size_t)(m0 + lrow) * K + lk4;
    const float* Bp = Bw    + (size_t)(n0 + lrow) * K + lk4;

    int tx = tid & 15, ty = tid >> 4;

    float acc[8][8];
#pragma unroll
    for (int i = 0; i < 8; i++)
#pragma unroll
        for (int j = 0; j < 8; j++) acc[i][j] = 0.0f;

    // preload tile 0
    {
        float4 av = *(const float4*)Ap;
        float4 bv = *(const float4*)Bp;
        As[0][lk4 + 0][lrow] = av.x; As[0][lk4 + 1][lrow] = av.y;
        As[0][lk4 + 2][lrow] = av.z; As[0][lk4 + 3][lrow] = av.w;
        Bs[0][lk4 + 0][lrow] = bv.x; Bs[0][lk4 + 1][lrow] = bv.y;
        Bs[0][lk4 + 2][lrow] = bv.z; Bs[0][lk4 + 3][lrow] = bv.w;
    }
    __syncthreads();

    int nk = K / BK;
    int buf = 0;
    for (int kt = 0; kt < nk; kt++) {
        float4 av2, bv2;
        bool pf = (kt + 1 < nk);
        if (pf) {
            av2 = *(const float4*)(Ap + (size_t)(kt + 1) * BK);
            bv2 = *(const float4*)(Bp + (size_t)(kt + 1) * BK);
        }
#pragma unroll
        for (int k = 0; k < BK; k++) {
            float a[8], b[8];
            *(float4*)&a[0] = *(const float4*)&As[buf][k][ty * 4];
            *(float4*)&a[4] = *(const float4*)&As[buf][k][ty * 4 + 64];
            *(float4*)&b[0] = *(const float4*)&Bs[buf][k][tx * 4];
            *(float4*)&b[4] = *(const float4*)&Bs[buf][k][tx * 4 + 64];
#pragma unroll
            for (int i = 0; i < 8; i++)
#pragma unroll
                for (int j = 0; j < 8; j++)
                    acc[i][j] = fmaf(a[i], b[j], acc[i][j]);
        }
        if (pf) {
            int nb = buf ^ 1;
            As[nb][lk4 + 0][lrow] = av2.x; As[nb][lk4 + 1][lrow] = av2.y;
            As[nb][lk4 + 2][lrow] = av2.z; As[nb][lk4 + 3][lrow] = av2.w;
            Bs[nb][lk4 + 0][lrow] = bv2.x; Bs[nb][lk4 + 1][lrow] = bv2.y;
            Bs[nb][lk4 + 2][lrow] = bv2.z; Bs[nb][lk4 + 3][lrow] = bv2.w;
        }
        __syncthreads();
        buf ^= 1;
    }

    if (EPI == 1) {
#pragma unroll
        for (int qi = 0; qi < 2; qi++)
#pragma unroll
            for (int i = 0; i < 4; i++) {
                int m = m0 + ty * 4 + qi * 64 + i;
#pragma unroll
                for (int qj = 0; qj < 2; qj++) {
                    int n = n0 + tx * 4 + qj * 64;
                    float4 v = make_float4(acc[qi * 4 + i][qj * 4 + 0],
                                           acc[qi * 4 + i][qj * 4 + 1],
                                           acc[qi * 4 + i][qj * 4 + 2],
                                           acc[qi * 4 + i][qj * 4 + 3]);
                    *(float4*)&C[(size_t)m * N + n] = v;
                }
            }
    } else {
        // scatter qkv output [m, n] -> Q/K/V [b, h, s, dd]
#pragma unroll
        for (int qi = 0; qi < 2; qi++)
#pragma unroll
            for (int i = 0; i < 4; i++) {
                int m = m0 + ty * 4 + qi * 64 + i;
                int b = m >> 11;           // / SEQ
                int s = m & (SEQ - 1);
#pragma unroll
                for (int qj = 0; qj < 2; qj++) {
                    int n = n0 + tx * 4 + qj * 64;
                    int which = n >> 10;   // 0=Q, 1=K, 2=V
                    int d = n & (DMODEL - 1);
                    int h = d >> 6;
                    int dd = d & (DH - 1);
                    float* dst = (which == 0) ? g_q : ((which == 1) ? g_k : g_v);
                    size_t idx = (((size_t)(b * NHEAD + h)) * SEQ + s) * DH + dd;
                    float4 v = make_float4(acc[qi * 4 + i][qj * 4 + 0],
                                           acc[qi * 4 + i][qj * 4 + 1],
                                           acc[qi * 4 + i][qj * 4 + 2],
                                           acc[qi * 4 + i][qj * 4 + 3]);
                    *(float4*)&dst[idx] = v;
                }
            }
    }
}

// ---------------------------------------------------------------------------
// Flash attention, fp32. Block = (q-tile of 64, one (b,h)). 256 threads,
// 4x4 microtiles, stride-65 smem. Online softmax (running max + sum).
// Causal: process only key tiles kt <= qt; mask only the diagonal tile.
// ---------------------------------------------------------------------------
#define ATTN_STRIDE 65
#define ATTN_SMEM (4 * 64 * ATTN_STRIDE * 4)   // Qs,Ks,Vs,Ps = 66560 bytes

__global__ __launch_bounds__(256) void attn_kernel() {
    extern __shared__ float sm[];
    float* Qs = sm;
    float* Ks = sm + 64 * ATTN_STRIDE;
    float* Vs = sm + 2 * 64 * ATTN_STRIDE;
    float* Ps = sm + 3 * 64 * ATTN_STRIDE;

    int tid = threadIdx.x;
    int qt = blockIdx.x;      // 0..31
    int bh = blockIdx.y;      // 0..31
    int q0 = qt * 64;

    const float* Qg = g_q + (((size_t)bh * SEQ) + q0) * DH;
    const float* Kg = g_k + ((size_t)bh * SEQ) * DH;
    const float* Vg = g_v + ((size_t)bh * SEQ) * DH;

    // load Q tile, pre-scaled by 1/sqrt(dh) = 0.125 (exact)
    for (int i = tid; i < 64 * 16; i += 256) {
        int r = i >> 4;
        int c4 = (i & 15) << 2;
        float4 v = *(const float4*)(Qg + r * DH + c4);
        float* p = &Qs[r * ATTN_STRIDE + c4];
        p[0] = v.x * 0.125f; p[1] = v.y * 0.125f;
        p[2] = v.z * 0.125f; p[3] = v.w * 0.125f;
    }

    int tx = tid & 15, ty = tid >> 4;
    int trow = ty * 4, tcol = tx * 4;

    float o[4][4];
    float mrow[4], lrow[4];
#pragma unroll
    for (int i = 0; i < 4; i++) {
        mrow[i] = -1e30f; lrow[i] = 0.0f;
#pragma unroll
        for (int j = 0; j < 4; j++) o[i][j] = 0.0f;
    }
    __syncthreads();

    int nkt = qt + 1;
    for (int kt = 0; kt < nkt; kt++) {
        int kb = kt * 64;
        // load K and V tiles
        const float* Kt = Kg + (size_t)kb * DH;
        const float* Vt = Vg + (size_t)kb * DH;
        for (int i = tid; i < 64 * 16; i += 256) {
            int r = i >> 4;
            int c4 = (i & 15) << 2;
            float4 kv = *(const float4*)(Kt + r * DH + c4);
            float* kp = &Ks[r * ATTN_STRIDE + c4];
            kp[0] = kv.x; kp[1] = kv.y; kp[2] = kv.z; kp[3] = kv.w;
            float4 vv = *(const float4*)(Vt + r * DH + c4);
            float* vp = &Vs[r * ATTN_STRIDE + c4];
            vp[0] = vv.x; vp[1] = vv.y; vp[2] = vv.z; vp[3] = vv.w;
        }
        __syncthreads();

        // scores S = Q * K^T for 4x4 microtile
        float sacc[4][4];
#pragma unroll
        for (int i = 0; i < 4; i++)
#pragma unroll
            for (int j = 0; j < 4; j++) sacc[i][j] = 0.0f;

        const float* q0p = &Qs[(trow + 0) * ATTN_STRIDE];
        const float* q1p = &Qs[(trow + 1) * ATTN_STRIDE];
        const float* q2p = &Qs[(trow + 2) * ATTN_STRIDE];
        const float* q3p = &Qs[(trow + 3) * ATTN_STRIDE];
        const float* k0p = &Ks[(tcol + 0) * ATTN_STRIDE];
        const float* k1p = &Ks[(tcol + 1) * ATTN_STRIDE];
        const float* k2p = &Ks[(tcol + 2) * ATTN_STRIDE];
        const float* k3p = &Ks[(tcol + 3) * ATTN_STRIDE];
#pragma unroll 8
        for (int d = 0; d < 64; d++) {
            float a0 = q0p[d], a1 = q1p[d], a2 = q2p[d], a3 = q3p[d];
            float b0 = k0p[d], b1 = k1p[d], b2 = k2p[d], b3 = k3p[d];
            sacc[0][0] = fmaf(a0, b0, sacc[0][0]); sacc[0][1] = fmaf(a0, b1, sacc[0][1]);
            sacc[0][2] = fmaf(a0, b2, sacc[0][2]); sacc[0][3] = fmaf(a0, b3, sacc[0][3]);
            sacc[1][0] = fmaf(a1, b0, sacc[1][0]); sacc[1][1] = fmaf(a1, b1, sacc[1][1]);
            sacc[1][2] = fmaf(a1, b2, sacc[1][2]); sacc[1][3] = fmaf(a1, b3, sacc[1][3]);
            sacc[2][0] = fmaf(a2, b0, sacc[2][0]); sacc[2][1] = fmaf(a2, b1, sacc[2][1]);
            sacc[2][2] = fmaf(a2, b2, sacc[2][2]); sacc[2][3] = fmaf(a2, b3, sacc[2][3]);
            sacc[3][0] = fmaf(a3, b0, sacc[3][0]); sacc[3][1] = fmaf(a3, b1, sacc[3][1]);
            sacc[3][2] = fmaf(a3, b2, sacc[3][2]); sacc[3][3] = fmaf(a3, b3, sacc[3][3]);
        }

        // causal mask only on the diagonal tile (kb == q0 there)
        if (kt == qt) {
#pragma unroll
            for (int i = 0; i < 4; i++)
#pragma unroll
                for (int j = 0; j < 4; j++)
                    if (tcol + j > trow + i) sacc[i][j] = -1e30f;
        }

        // online softmax. Rows trow..trow+3 are owned by a 16-lane group.
        float pm[4];
#pragma unroll
        for (int i = 0; i < 4; i++)
            pm[i] = fmaxf(fmaxf(sacc[i][0], sacc[i][1]), fmaxf(sacc[i][2], sacc[i][3]));
#pragma unroll
        for (int dlt = 1; dlt < 16; dlt <<= 1)
#pragma unroll
            for (int i = 0; i < 4; i++)
                pm[i] = fmaxf(pm[i], __shfl_xor_sync(0xffffffffu, pm[i], dlt));

        float corr[4], psum[4];
#pragma unroll
        for (int i = 0; i < 4; i++) {
            float nm = fmaxf(mrow[i], pm[i]);
            corr[i] = __expf(mrow[i] - nm);
            mrow[i] = nm;
            psum[i] = 0.0f;
        }
#pragma unroll
        for (int i = 0; i < 4; i++) {
            float* pr = &Ps[(trow + i) * ATTN_STRIDE + tcol];
#pragma unroll
            for (int j = 0; j < 4; j++) {
                float p = __expf(sacc[i][j] - mrow[i]);
                pr[j] = p;
                psum[i] += p;
            }
        }
#pragma unroll
        for (int dlt = 1; dlt < 16; dlt <<= 1)
#pragma unroll
            for (int i = 0; i < 4; i++)
                psum[i] += __shfl_xor_sync(0xffffffffu, psum[i], dlt);
#pragma unroll
        for (int i = 0; i < 4; i++) {
            lrow[i] = lrow[i] * corr[i] + psum[i];
#pragma unroll
            for (int j = 0; j < 4; j++) o[i][j] *= corr[i];
        }
        __syncwarp();   // Ps rows are produced within this 16-lane group's warp

        // O += P * V
        const float* p0p = &Ps[(trow + 0) * ATTN_STRIDE];
        const float* p1p = &Ps[(trow + 1) * ATTN_STRIDE];
        const float* p2p = &Ps[(trow + 2) * ATTN_STRIDE];
        const float* p3p = &Ps[(trow + 3) * ATTN_STRIDE];
        const float* vc = &Vs[tcol];
#pragma unroll 8
        for (int k2 = 0; k2 < 64; k2++) {
            float a0 = p0p[k2], a1 = p1p[k2], a2 = p2p[k2], a3 = p3p[k2];
            const float* vr = vc + k2 * ATTN_STRIDE;
            float b0 = vr[0], b1 = vr[1], b2 = vr[2], b3 = vr[3];
            o[0][0] = fmaf(a0, b0, o[0][0]); o[0][1] = fmaf(a0, b1, o[0][1]);
            o[0][2] = fmaf(a0, b2, o[0][2]); o[0][3] = fmaf(a0, b3, o[0][3]);
            o[1][0] = fmaf(a1, b0, o[1][0]); o[1][1] = fmaf(a1, b1, o[1][1]);
            o[1][2] = fmaf(a1, b2, o[1][2]); o[1][3] = fmaf(a1, b3, o[1][3]);
            o[2][0] = fmaf(a2, b0, o[2][0]); o[2][1] = fmaf(a2, b1, o[2][1]);
            o[2][2] = fmaf(a2, b2, o[2][2]); o[2][3] = fmaf(a2, b3, o[2][3]);
            o[3][0] = fmaf(a3, b0, o[3][0]); o[3][1] = fmaf(a3, b1, o[3][1]);
            o[3][2] = fmaf(a3, b2, o[3][2]); o[3][3] = fmaf(a3, b3, o[3][3]);
        }
        __syncthreads();   // before next tile's loads overwrite Ks/Vs
    }

    // write attn output in [B, S, D] layout (head-merged)
    int b = bh >> 4, h = bh & 15;
#pragma unroll
    for (int i = 0; i < 4; i++) {
        int q = q0 + trow + i;
        float inv = 1.0f / lrow[i];
        float4 v = make_float4(o[i][0] * inv, o[i][1] * inv,
                               o[i][2] * inv, o[i][3] * inv);
        size_t idx = (((size_t)b * SEQ) + q) * DMODEL + h * DH + tcol;
        *(float4*)&g_attn[idx] = v;
    }
}

// ---------------------------------------------------------------------------
// Launch
// ---------------------------------------------------------------------------
extern "C" void kernel_launch(void* const* d_in, const int* in_sizes, int n_in,
                              void* d_out, int out_size)
{
    (void)in_sizes; (void)n_in; (void)out_size;
    const float* X    = (const float*)d_in[0];
    const int*   pos  = (const int*)d_in[1];
    const float* Wqkv = (const float*)d_in[2];
    const float* Wo   = (const float*)d_in[3];
    float* out = (float*)d_out;

    cudaFuncSetAttribute(attn_kernel, cudaFuncAttributeMaxDynamicSharedMemorySize,
                         ATTN_SMEM);

    // 1. RoPE tables
    rope_table_kernel<<<(SEQ * HALF + 255) / 256, 256>>>(pos);

    // 2. QKV projection (scatter into Q/K/V head layout)
    dim3 g1(3 * DMODEL / BN, MROWS / BM);
    sgemm_kernel<0><<<g1, 256>>>(X, Wqkv, nullptr, MROWS, 3 * DMODEL, DMODEL);

    // 3. RoPE on Q and K
    rope_apply_kernel<<<(BH * SEQ * HALF + 255) / 256, 256>>>();

    // 4. Causal flash attention
    dim3 g2(SEQ / 64, BH);
    attn_kernel<<<g2, 256, ATTN_SMEM>>>();

    // 5. Output projection
    dim3 g3(DMODEL / BN, MROWS / BM);
    sgemm_kernel<1><<<g3, 256>>>(nullptr, Wo, out, MROWS, DMODEL, DMODEL);
}

// round 17
// speedup vs baseline: 1.0438x; 1.0438x over previous
#include <cuda_runtime.h>
#include <cuda_bf16.h>
#include <math.h>

// Problem constants
#define BATCH   2
#define SEQ     2048
#define DMODEL  1024
#define NHEAD   16
#define DH      64
#define HALF    32
#define MROWS   (BATCH * SEQ)     // 4096 tokens
#define BH      (BATCH * NHEAD)   // 32

// Scratch (device globals; no allocation allowed)
__device__ float g_q[(size_t)BH * SEQ * DH];        // 16 MB
__device__ float g_k[(size_t)BH * SEQ * DH];        // 16 MB
__device__ float g_v[(size_t)BH * SEQ * DH];        // 16 MB
__device__ float g_attn[(size_t)MROWS * DMODEL];    // 16 MB
__device__ float g_cos[SEQ * HALF];
__device__ float g_sin[SEQ * HALF];

// ---------------------------------------------------------------------------
// RoPE cos/sin table. Matches reference: inv_freq = theta^(-2j/64) (fp32),
// ang = fp32(pos * inv_freq), then accurate cos/sin of that fp32 angle.
// ---------------------------------------------------------------------------
__global__ void rope_table_kernel(const int* __restrict__ pos) {
    int i = blockIdx.x * blockDim.x + threadIdx.x;
    if (i >= SEQ * HALF) return;
    int s = i >> 5;
    int j = i & 31;
    double invd = pow(10000.0, -(double)(2 * j) / (double)DH);
    float invf = (float)invd;
    float ang = (float)pos[s] * invf;     // exact fp32 product, like reference
    double a = (double)ang;
    g_cos[i] = (float)cos(a);
    g_sin[i] = (float)sin(a);
}

// ---------------------------------------------------------------------------
// Apply RoPE in place to g_q and g_k. Pairing is adjacent elements (2j, 2j+1).
// ---------------------------------------------------------------------------
__global__ void rope_apply_kernel() {
    int i = blockIdx.x * blockDim.x + threadIdx.x;
    const int total = BH * SEQ * HALF;   // 2,097,152
    if (i >= total) return;
    int j  = i & 31;
    int s  = (i >> 5) & (SEQ - 1);
    int bh = i >> 16;                    // / (SEQ*HALF)
    float c  = g_cos[(s << 5) + j];
    float sn = g_sin[(s << 5) + j];
    size_t base = (((size_t)bh * SEQ) + s) * DH + 2 * j;
    float2 q = *(float2*)(g_q + base);
    float2 k = *(float2*)(g_k + base);
    float2 qo, ko;
    qo.x = q.x * c - q.y * sn;  qo.y = q.x * sn + q.y * c;
    ko.x = k.x * c - k.y * sn;  ko.y = k.x * sn + k.y * c;
    *(float2*)(g_q + base) = qo;
    *(float2*)(g_k + base) = ko;
}

// ---------------------------------------------------------------------------
// SGEMM: C[m,n] = sum_k A[m,k] * Bw[n,k]   (both operands K-major row-major)
// 128x128 tile, BK=8, 256 threads, 8x8 microtile in 4 quadrants (float4 LDS,
// conflict-free), double-buffered smem with register prefetch.
// EPI=0: scatter into g_q/g_k/g_v ([B,H,S,dh] layout). EPI=1: plain row-major C.
// ---------------------------------------------------------------------------
#define BM 128
#define BN 128
#define BK 8

template <int EPI>
__global__ __launch_bounds__(256) void sgemm_kernel(
    const float* __restrict__ A, const float* __restrict__ Bw,
    float* __restrict__ C, int M, int N, int K)
{
    __shared__ float As[2][BK][BM];
    __shared__ float Bs[2][BK][BN];

    const float* Abase = (EPI == 1) ? (const float*)g_attn : A;

    int tid = threadIdx.x;
    int m0 = blockIdx.y * BM;
    int n0 = blockIdx.x * BN;

    int lrow = tid >> 1;              // 0..127
    int lk4  = (tid & 1) * 4;         // 0 or 4
    const float* Ap = Abase + (size_t)(m0 + lrow) * K + lk4;
    const float* Bp = Bw    + (size_t)(n0 + lrow) * K + lk4;

    int tx = tid & 15, ty = tid >> 4;

    float acc[8][8];
#pragma unroll
    for (int i = 0; i < 8; i++)
#pragma unroll
        for (int j = 0; j < 8; j++) acc[i][j] = 0.0f;

    // preload tile 0
    {
        float4 av = *(const float4*)Ap;
        float4 bv = *(const float4*)Bp;
        As[0][lk4 + 0][lrow] = av.x; As[0][lk4 + 1][lrow] = av.y;
        As[0][lk4 + 2][lrow] = av.z; As[0][lk4 + 3][lrow] = av.w;
        Bs[0][lk4 + 0][lrow] = bv.x; Bs[0][lk4 + 1][lrow] = bv.y;
        Bs[0][lk4 + 2][lrow] = bv.z; Bs[0][lk4 + 3][lrow] = bv.w;
    }
    __syncthreads();

    int nk = K / BK;
    int buf = 0;
    for (int kt = 0; kt < nk; kt++) {
        float4 av2, bv2;
        bool pf = (kt + 1 < nk);
        if (pf) {
            av2 = *(const float4*)(Ap + (size_t)(kt + 1) * BK);
            bv2 = *(const float4*)(Bp + (size_t)(kt + 1) * BK);
        }
#pragma unroll
        for (int k = 0; k < BK; k++) {
            float a[8], b[8];
            *(float4*)&a[0] = *(const float4*)&As[buf][k][ty * 4];
            *(float4*)&a[4] = *(const float4*)&As[buf][k][ty * 4 + 64];
            *(float4*)&b[0] = *(const float4*)&Bs[buf][k][tx * 4];
            *(float4*)&b[4] = *(const float4*)&Bs[buf][k][tx * 4 + 64];
#pragma unroll
            for (int i = 0; i < 8; i++)
#pragma unroll
                for (int j = 0; j < 8; j++)
                    acc[i][j] = fmaf(a[i], b[j], acc[i][j]);
        }
        if (pf) {
            int nb = buf ^ 1;
            As[nb][lk4 + 0][lrow] = av2.x; As[nb][lk4 + 1][lrow] = av2.y;
            As[nb][lk4 + 2][lrow] = av2.z; As[nb][lk4 + 3][lrow] = av2.w;
            Bs[nb][lk4 + 0][lrow] = bv2.x; Bs[nb][lk4 + 1][lrow] = bv2.y;
            Bs[nb][lk4 + 2][lrow] = bv2.z; Bs[nb][lk4 + 3][lrow] = bv2.w;
        }
        __syncthreads();
        buf ^= 1;
    }

    if (EPI == 1) {
#pragma unroll
        for (int qi = 0; qi < 2; qi++)
#pragma unroll
            for (int i = 0; i < 4; i++) {
                int m = m0 + ty * 4 + qi * 64 + i;
#pragma unroll
                for (int qj = 0; qj < 2; qj++) {
                    int n = n0 + tx * 4 + qj * 64;
                    float4 v = make_float4(acc[qi * 4 + i][qj * 4 + 0],
                                           acc[qi * 4 + i][qj * 4 + 1],
                                           acc[qi * 4 + i][qj * 4 + 2],
                                           acc[qi * 4 + i][qj * 4 + 3]);
                    *(float4*)&C[(size_t)m * N + n] = v;
                }
            }
    } else {
        // scatter qkv output [m, n] -> Q/K/V [b, h, s, dd]
#pragma unroll
        for (int qi = 0; qi < 2; qi++)
#pragma unroll
            for (int i = 0; i < 4; i++) {
                int m = m0 + ty * 4 + qi * 64 + i;
                int b = m >> 11;           // / SEQ
                int s = m & (SEQ - 1);
#pragma unroll
                for (int qj = 0; qj < 2; qj++) {
                    int n = n0 + tx * 4 + qj * 64;
                    int which = n >> 10;   // 0=Q, 1=K, 2=V
                    int d = n & (DMODEL - 1);
                    int h = d >> 6;
                    int dd = d & (DH - 1);
                    float* dst = (which == 0) ? g_q : ((which == 1) ? g_k : g_v);
                    size_t idx = (((size_t)(b * NHEAD + h)) * SEQ + s) * DH + dd;
                    float4 v = make_float4(acc[qi * 4 + i][qj * 4 + 0],
                                           acc[qi * 4 + i][qj * 4 + 1],
                                           acc[qi * 4 + i][qj * 4 + 2],
                                           acc[qi * 4 + i][qj * 4 + 3]);
                    *(float4*)&dst[idx] = v;
                }
            }
    }
}

// ---------------------------------------------------------------------------
// Flash attention, fp32. Block = (q-tile of 64, one (b,h)). 256 threads,
// 4x4 microtiles. All compute-loop shared traffic is aligned LDS.128:
//   Qs  [row][d]   stride 64: row float4 reads along d (broadcast over tx)
//   Kst [d][key]   stride 68: TRANSPOSED; one float4 read at [d][tcol]
//                  yields keys tcol..tcol+3 at depth d. Offsets = 68*d + 4*tx
//                  -> 16B aligned, consecutive lanes -> conflict-free.
//   Vs  [key][d]   stride 64: row float4 reads
//   Ps  [row][key] stride 68 (mult of 4 -> rows 16B aligned)
// The K transpose happens in the loader via scalar stores (bounded conflicts,
// off the critical path). Online softmax (running max + sum). Causal: only
// key tiles kt <= qt; mask only the diagonal tile. Blocks in reverse qt
// order so the longest (triangular) blocks are scheduled first.
// ---------------------------------------------------------------------------
#define QS_STR 64
#define KST_STR 68
#define VS_STR 64
#define PS_STR 68
#define ATTN_SMEM ((64 * QS_STR + 64 * KST_STR + 64 * VS_STR + 64 * PS_STR) * 4) // 67584 B

__global__ __launch_bounds__(256, 3) void attn_kernel() {
    extern __shared__ float sm[];
    float* Qs  = sm;
    float* Kst = Qs + 64 * QS_STR;
    float* Vs  = Kst + 64 * KST_STR;
    float* Ps  = Vs + 64 * VS_STR;

    int tid = threadIdx.x;
    int qt = (int)(gridDim.x - 1u) - (int)blockIdx.x;   // reversed: long blocks first
    int bh = blockIdx.y;
    int q0 = qt * 64;

    const float* Qg = g_q + (((size_t)bh * SEQ) + q0) * DH;
    const float* Kg = g_k + ((size_t)bh * SEQ) * DH;
    const float* Vg = g_v + ((size_t)bh * SEQ) * DH;

    // load Q tile, pre-scaled by 1/sqrt(dh) = 0.125 (exact)
    for (int i = tid; i < 64 * 16; i += 256) {
        int r = i >> 4;
        int c4 = (i & 15) << 2;
        float4 v = *(const float4*)(Qg + r * DH + c4);
        v.x *= 0.125f; v.y *= 0.125f; v.z *= 0.125f; v.w *= 0.125f;
        *(float4*)&Qs[r * QS_STR + c4] = v;
    }

    int tx = tid & 15, ty = tid >> 4;
    int trow = ty * 4, tcol = tx * 4;

    float o[4][4];
    float mrow[4], lrow[4];
#pragma unroll
    for (int i = 0; i < 4; i++) {
        mrow[i] = -1e30f; lrow[i] = 0.0f;
#pragma unroll
        for (int j = 0; j < 4; j++) o[i][j] = 0.0f;
    }
    __syncthreads();

    int nkt = qt + 1;
    for (int kt = 0; kt < nkt; kt++) {
        int kb = kt * 64;
        const float* Kt = Kg + (size_t)kb * DH;
        const float* Vt = Vg + (size_t)kb * DH;
        // K: coalesced float4 gmem read, transposed scalar smem stores.
        // V: coalesced float4 gmem read, float4 smem store (stride 64).
        for (int i = tid; i < 64 * 16; i += 256) {
            int r = i >> 4;              // key index 0..63
            int c4 = (i & 15) << 2;      // d offset 0..60
            float4 kv = *(const float4*)(Kt + r * DH + c4);
            Kst[(c4 + 0) * KST_STR + r] = kv.x;
            Kst[(c4 + 1) * KST_STR + r] = kv.y;
            Kst[(c4 + 2) * KST_STR + r] = kv.z;
            Kst[(c4 + 3) * KST_STR + r] = kv.w;
            float4 vv = *(const float4*)(Vt + r * DH + c4);
            *(float4*)&Vs[r * VS_STR + c4] = vv;
        }
        __syncthreads();

        // scores S = Q * K^T for 4x4 microtile; float4 along d for Q,
        // float4 along key (from transposed K) at 4 consecutive depths.
        float sacc[4][4];
#pragma unroll
        for (int i = 0; i < 4; i++)
#pragma unroll
            for (int j = 0; j < 4; j++) sacc[i][j] = 0.0f;

#pragma unroll 4
        for (int d = 0; d < 64; d += 4) {
            float4 k0 = *(const float4*)&Kst[(d + 0) * KST_STR + tcol];
            float4 k1 = *(const float4*)&Kst[(d + 1) * KST_STR + tcol];
            float4 k2 = *(const float4*)&Kst[(d + 2) * KST_STR + tcol];
            float4 k3 = *(const float4*)&Kst[(d + 3) * KST_STR + tcol];
#pragma unroll
            for (int i = 0; i < 4; i++) {
                float4 a = *(const float4*)&Qs[(trow + i) * QS_STR + d];
                sacc[i][0] = fmaf(a.x, k0.x, sacc[i][0]);
                sacc[i][0] = fmaf(a.y, k1.x, sacc[i][0]);
                sacc[i][0] = fmaf(a.z, k2.x, sacc[i][0]);
                sacc[i][0] = fmaf(a.w, k3.x, sacc[i][0]);
                sacc[i][1] = fmaf(a.x, k0.y, sacc[i][1]);
                sacc[i][1] = fmaf(a.y, k1.y, sacc[i][1]);
                sacc[i][1] = fmaf(a.z, k2.y, sacc[i][1]);
                sacc[i][1] = fmaf(a.w, k3.y, sacc[i][1]);
                sacc[i][2] = fmaf(a.x, k0.z, sacc[i][2]);
                sacc[i][2] = fmaf(a.y, k1.z, sacc[i][2]);
                sacc[i][2] = fmaf(a.z, k2.z, sacc[i][2]);
                sacc[i][2] = fmaf(a.w, k3.z, sacc[i][2]);
                sacc[i][3] = fmaf(a.x, k0.w, sacc[i][3]);
                sacc[i][3] = fmaf(a.y, k1.w, sacc[i][3]);
                sacc[i][3] = fmaf(a.z, k2.w, sacc[i][3]);
                sacc[i][3] = fmaf(a.w, k3.w, sacc[i][3]);
            }
        }

        // causal mask only on the diagonal tile
        if (kt == qt) {
#pragma unroll
            for (int i = 0; i < 4; i++)
#pragma unroll
                for (int j = 0; j < 4; j++)
                    if (tcol + j > trow + i) sacc[i][j] = -1e30f;
        }

        // online softmax: rows trow..trow+3 owned by a 16-lane group
        float pm[4];
#pragma unroll
        for (int i = 0; i < 4; i++)
            pm[i] = fmaxf(fmaxf(sacc[i][0], sacc[i][1]), fmaxf(sacc[i][2], sacc[i][3]));
#pragma unroll
        for (int dlt = 1; dlt < 16; dlt <<= 1)
#pragma unroll
            for (int i = 0; i < 4; i++)
                pm[i] = fmaxf(pm[i], __shfl_xor_sync(0xffffffffu, pm[i], dlt));

        float corr[4], psum[4];
#pragma unroll
        for (int i = 0; i < 4; i++) {
            float nm = fmaxf(mrow[i], pm[i]);
            corr[i] = __expf(mrow[i] - nm);
            mrow[i] = nm;
        }
#pragma unroll
        for (int i = 0; i < 4; i++) {
            float4 p;
            p.x = __expf(sacc[i][0] - mrow[i]);
            p.y = __expf(sacc[i][1] - mrow[i]);
            p.z = __expf(sacc[i][2] - mrow[i]);
            p.w = __expf(sacc[i][3] - mrow[i]);
            psum[i] = (p.x + p.y) + (p.z + p.w);
            *(float4*)&Ps[(trow + i) * PS_STR + tcol] = p;
        }
#pragma unroll
        for (int dlt = 1; dlt < 16; dlt <<= 1)
#pragma unroll
            for (int i = 0; i < 4; i++)
                psum[i] += __shfl_xor_sync(0xffffffffu, psum[i], dlt);
#pragma unroll
        for (int i = 0; i < 4; i++) {
            lrow[i] = lrow[i] * corr[i] + psum[i];
#pragma unroll
            for (int j = 0; j < 4; j++) o[i][j] *= corr[i];
        }
        __syncwarp();   // Ps rows are produced within this warp's 16-lane groups

        // O += P * V, float4 along k
#pragma unroll 4
        for (int k2 = 0; k2 < 64; k2 += 4) {
            float4 v0 = *(const float4*)&Vs[(k2 + 0) * VS_STR + tcol];
            float4 v1 = *(const float4*)&Vs[(k2 + 1) * VS_STR + tcol];
            float4 v2 = *(const float4*)&Vs[(k2 + 2) * VS_STR + tcol];
            float4 v3 = *(const float4*)&Vs[(k2 + 3) * VS_STR + tcol];
#pragma unroll
            for (int i = 0; i < 4; i++) {
                float4 p = *(const float4*)&Ps[(trow + i) * PS_STR + k2];
                o[i][0] = fmaf(p.x, v0.x, o[i][0]);
                o[i][0] = fmaf(p.y, v1.x, o[i][0]);
                o[i][0] = fmaf(p.z, v2.x, o[i][0]);
                o[i][0] = fmaf(p.w, v3.x, o[i][0]);
                o[i][1] = fmaf(p.x, v0.y, o[i][1]);
                o[i][1] = fmaf(p.y, v1.y, o[i][1]);
                o[i][1] = fmaf(p.z, v2.y, o[i][1]);
                o[i][1] = fmaf(p.w, v3.y, o[i][1]);
                o[i][2] = fmaf(p.x, v0.z, o[i][2]);
                o[i][2] = fmaf(p.y, v1.z, o[i][2]);
                o[i][2] = fmaf(p.z, v2.z, o[i][2]);
                o[i][2] = fmaf(p.w, v3.z, o[i][2]);
                o[i][3] = fmaf(p.x, v0.w, o[i][3]);
                o[i][3] = fmaf(p.y, v1.w, o[i][3]);
                o[i][3] = fmaf(p.z, v2.w, o[i][3]);
                o[i][3] = fmaf(p.w, v3.w, o[i][3]);
            }
        }
        __syncthreads();   // before next tile's loads overwrite Kst/Vs
    }

    // write attn output in [B, S, D] layout (head-merged)
    int b = bh >> 4, h = bh & 15;
#pragma unroll
    for (int i = 0; i < 4; i++) {
        int q = q0 + trow + i;
        float inv = 1.0f / lrow[i];
        float4 v = make_float4(o[i][0] * inv, o[i][1] * inv,
                               o[i][2] * inv, o[i][3] * inv);
        size_t idx = (((size_t)b * SEQ) + q) * DMODEL + h * DH + tcol;
        *(float4*)&g_attn[idx] = v;
    }
}

// ---------------------------------------------------------------------------
// Launch
// ---------------------------------------------------------------------------
extern "C" void kernel_launch(void* const* d_in, const int* in_sizes, int n_in,
                              void* d_out, int out_size)
{
    (void)in_sizes; (void)n_in; (void)out_size;
    const float* X    = (const float*)d_in[0];
    const int*   pos  = (const int*)d_in[1];
    const float* Wqkv = (const float*)d_in[2];
    const float* Wo   = (const float*)d_in[3];
    float* out = (float*)d_out;

    cudaFuncSetAttribute(attn_kernel, cudaFuncAttributeMaxDynamicSharedMemorySize,
                         ATTN_SMEM);

    // 1. RoPE tables
    rope_table_kernel<<<(SEQ * HALF + 255) / 256, 256>>>(pos);

    // 2. QKV projection (scatter into Q/K/V head layout)
    dim3 g1(3 * DMODEL / BN, MROWS / BM);
    sgemm_kernel<0><<<g1, 256>>>(X, Wqkv, nullptr, MROWS, 3 * DMODEL, DMODEL);

    // 3. RoPE on Q and K
    rope_apply_kernel<<<(BH * SEQ * HALF + 255) / 256, 256>>>();

    // 4. Causal flash attention
    dim3 g2(SEQ / 64, BH);
    attn_kernel<<<g2, 256, ATTN_SMEM>>>();

    // 5. Output projection
    dim3 g3(DMODEL / BN, MROWS / BM);
    sgemm_kernel<1><<<g3, 256>>>(nullptr, Wo, out, MROWS, DMODEL, DMODEL);
}